// round 7
// baseline (speedup 1.0000x reference)
#include <cuda_runtime.h>
#include <cstdint>

#define NN   50000
#define DEG  16
#define FD   160
#define HD   160
#define GD   640          // 4*H
#define OC   128
#define KHH  160          // K of recurrence GEMM

#define TM   64           // nodes per CTA
#define NT   512          // threads
#define NW   16           // warps: 8 row-groups x 2 gate-halves
#define RPG  8            // rows per group (warp pair)
#define KC   16
#define NCH  (KHH/KC)     // 10
#define CHF  (KC*GD)      // floats per chunk = 10240
#define CHB  (CHF*4)      // bytes per chunk  = 40960

// ---------------- device scratch ----------------
__device__ float g_hin[NN * FD];
// weight layout: [k][gsel][m][pair]  gsel0 pair=(i,f), gsel1 pair=(g,o)
__device__ float g_WihP[KHH * GD];
__device__ float g_WhhP[KHH * GD];
__device__ float g_bias[GD];             // [gsel][m][pair]
__device__ float g_WlP[KHH * OC];        // [k][j]
__device__ float g_WrP[KHH * OC];        // [k][j]
__device__ float g_P[NN * GD];           // [node][gsel][m][pair]
__device__ float g_Q[NN * OC];           // hin@Wr + b_l

// ---------------- helpers ----------------
typedef unsigned long long ull;

__device__ __forceinline__ ull pack2(float lo, float hi) {
    ull v; asm("mov.b64 %0, {%1, %2};" : "=l"(v) : "f"(lo), "f"(hi)); return v;
}
__device__ __forceinline__ void unpack2(ull v, float& lo, float& hi) {
    asm("mov.b64 {%0, %1}, %2;" : "=f"(lo), "=f"(hi) : "l"(v));
}
__device__ __forceinline__ void fma2(ull& d, ull a, ull b) {
    asm("fma.rn.f32x2 %0, %1, %2, %0;" : "+l"(d) : "l"(a), "l"(b));
}
__device__ __forceinline__ ull lds64(uint32_t a) {
    ull v; asm("ld.shared.b64 %0, [%1];" : "=l"(v) : "r"(a)); return v;
}
__device__ __forceinline__ void cp16(uint32_t s, const void* g) {
    asm volatile("cp.async.ca.shared.global [%0], [%1], 16;" :: "r"(s), "l"(g));
}
__device__ __forceinline__ void cpcommit() { asm volatile("cp.async.commit_group;"); }
template<int N> __device__ __forceinline__ void cpwait() {
    asm volatile("cp.async.wait_group %0;" :: "n"(N));
}
__device__ __forceinline__ float sigm(float x) {
    return __fdividef(1.f, 1.f + __expf(-x));
}
__device__ __forceinline__ float tanhfast(float x) {
    return __fdividef(2.f, 1.f + __expf(-2.f * x)) - 1.f;
}

// NT=512: each thread copies 20 floats (5 x 16B) of a 40960B chunk
__device__ __forceinline__ void stage_chunk(const float* gsrc, uint32_t sdst, int tid) {
#pragma unroll
    for (int u = 0; u < 5; u++)
        cp16(sdst + (uint32_t)(tid * 16 + u * 8192), gsrc + tid * 4 + u * 2048);
    cpcommit();
}

// K=160 GEMM, gate-split: warp computes ONE gate pair (gsel) for 8 rows.
// acc[i][n] : row i, m = n*32+c, pair (lo,hi) = gates (2*gsel, 2*gsel+1)
__device__ __forceinline__ void gemm160(const float* __restrict__ gW, uint32_t wsbase,
                                        const float* __restrict__ hrow, int tid, int c,
                                        int gsel, ull acc[RPG][5]) {
    stage_chunk(gW, wsbase, tid);
    stage_chunk(gW + CHF, wsbase + CHB, tid);
    const uint32_t lbase = (uint32_t)(gsel * 1280 + c * 8);
    for (int ch = 0; ch < NCH; ch++) {
        if (ch == NCH - 1) cpwait<0>(); else cpwait<1>();
        __syncthreads();
        const uint32_t wb0 = wsbase + (uint32_t)(ch & 1) * CHB + lbase;
#pragma unroll
        for (int kh = 0; kh < KC / 2; kh++) {
            float2 af[RPG];
#pragma unroll
            for (int i = 0; i < RPG; i++)
                af[i] = *(const float2*)&hrow[i * KHH + ch * KC + kh * 2];
#pragma unroll
            for (int k2 = 0; k2 < 2; k2++) {
                ull a2[RPG];
#pragma unroll
                for (int i = 0; i < RPG; i++) {
                    float a = k2 ? af[i].y : af[i].x;
                    a2[i] = pack2(a, a);
                }
                const uint32_t wb = wb0 + (uint32_t)((kh * 2 + k2) * 2560);
#pragma unroll
                for (int n = 0; n < 5; n++) {
                    ull w = lds64(wb + (uint32_t)(n * 256));
#pragma unroll
                    for (int i = 0; i < RPG; i++) fma2(acc[i][n], a2[i], w);
                }
            }
        }
        __syncthreads();
        if (ch < NCH - 2) stage_chunk(gW + (ch + 2) * CHF, wsbase + (uint32_t)(ch & 1) * CHB, tid);
    }
}

// ---------------- prep kernels ----------------
__global__ void prep_hin(const float* __restrict__ x, const int* __restrict__ tids,
                         const float* __restrict__ emb) {
    int i = blockIdx.x * blockDim.x + threadIdx.x;
    if (i >= NN * FD) return;
    int n = i / FD, c = i % FD;
    g_hin[i] = (c < 128) ? x[n * 128 + c] : emb[tids[n] * 32 + (c - 128)];
}

__global__ void prep_w(const float* __restrict__ Wih, const float* __restrict__ Whh,
                       const float* __restrict__ bih, const float* __restrict__ bhh,
                       const float* __restrict__ Wl,  const float* __restrict__ Wr) {
    int i = blockIdx.x * blockDim.x + threadIdx.x;
    if (i < KHH * GD) {
        int k = i / GD, r = i % GD;
        int gs = r / 320, q = r % 320, m = q >> 1, p = q & 1;
        int gate = gs * 2 + p;
        int j = gate * HD + m;
        g_WihP[i] = Wih[j * FD + k];
        g_WhhP[i] = Whh[j * HD + k];
    }
    if (i < GD) {
        int gs = i / 320, q = i % 320, m = q >> 1, p = q & 1;
        int gate = gs * 2 + p;
        g_bias[i] = bih[gate * HD + m] + bhh[gate * HD + m];
    }
    if (i < KHH * OC) {
        int k = i / OC, j = i % OC;
        g_WlP[i] = Wl[j * FD + k];
        g_WrP[i] = Wr[j * FD + k];
    }
}

// P = hin@Wih^T + b (plane-split layout) ; Q = hin@Wr^T + b_l
__global__ void __launch_bounds__(NT, 1)
prep_PQ(const float* __restrict__ bl) {
    extern __shared__ float sm[];
    float* hs = sm;                       // [64][160]
    const uint32_t sbase = (uint32_t)__cvta_generic_to_shared(sm);
    const uint32_t wsbase = sbase + TM * KHH * 4;

    const int tid = threadIdx.x, c = tid & 31, warp = tid >> 5;
    const int rg = warp >> 1, gsel = warp & 1;
    const int nodeBase = blockIdx.x * TM;
    float* hrow = hs + rg * RPG * KHH;

    // load hin rows (clamped): 2560 float4 total
#pragma unroll
    for (int u = 0; u < 5; u++) {
        int idx4 = tid + u * NT;
        int r = idx4 / 40, col4 = idx4 % 40;
        int node = nodeBase + r; if (node >= NN) node = NN - 1;
        ((float4*)hs)[idx4] = ((const float4*)g_hin)[node * 40 + col4];
    }
    __syncthreads();

    ull acc[RPG][5];
    const ull* b8 = (const ull*)g_bias;
#pragma unroll
    for (int n = 0; n < 5; n++) {
        ull b = b8[gsel * 160 + n * 32 + c];
#pragma unroll
        for (int i = 0; i < RPG; i++) acc[i][n] = b;
    }
    gemm160(g_WihP, wsbase, hrow, tid, c, gsel, acc);

    ull* P8 = (ull*)g_P;
#pragma unroll
    for (int i = 0; i < RPG; i++) {
        int node = nodeBase + rg * RPG + i;
        if (node < NN) {
#pragma unroll
            for (int n = 0; n < 5; n++)
                P8[node * 320 + gsel * 160 + n * 32 + c] = acc[i][n];
        }
    }

    // ---- Q phase: stage full Wr into Ws region; each warp does 4 rows
    __syncthreads();
    float* Wfs = hs + TM * KHH;
    for (int u = tid; u < KHH * OC / 4; u += NT)
        ((float4*)Wfs)[u] = ((const float4*)g_WrP)[u];
    __syncthreads();

    float4 q[4];
    float4 blv = ((const float4*)bl)[c];
#pragma unroll
    for (int i = 0; i < 4; i++) q[i] = blv;
    for (int k = 0; k < KHH; k++) {
        float4 w = ((const float4*)Wfs)[k * 32 + c];
#pragma unroll
        for (int i = 0; i < 4; i++) {
            float a = hrow[(gsel * 4 + i) * KHH + k];
            q[i].x = fmaf(a, w.x, q[i].x);
            q[i].y = fmaf(a, w.y, q[i].y);
            q[i].z = fmaf(a, w.z, q[i].z);
            q[i].w = fmaf(a, w.w, q[i].w);
        }
    }
#pragma unroll
    for (int i = 0; i < 4; i++) {
        int node = nodeBase + rg * RPG + gsel * 4 + i;
        if (node < NN) ((float4*)g_Q)[node * 32 + c] = q[i];
    }
}

// ---------------- main recurrence kernel ----------------
// smem: hs[64*160] | Ws[2][10240] (doubles as exchange buffer) | cst[20*512] | src[64]
#define SM_MAIN (TM*KHH*4 + 2*CHB + 20*NT*4 + TM*4)

__global__ void __launch_bounds__(NT, 1)
lstm_main(const int* __restrict__ esrc, float* __restrict__ out) {
    extern __shared__ float sm[];
    float* hs   = sm;
    ull*   exch = (ull*)(sm + TM * KHH);        // aliases Ws region (dead between GEMMs)
    float* cstS = sm + TM * KHH + 2 * CHF;
    int*   srcS = (int*)(cstS + 20 * NT);
    const uint32_t sbase  = (uint32_t)__cvta_generic_to_shared(sm);
    const uint32_t wsbase = sbase + TM * KHH * 4;

    const int tid = threadIdx.x, c = tid & 31, warp = tid >> 5;
    const int rg = warp >> 1, gsel = warp & 1;
    const int nodeBase = blockIdx.x * TM;
    float* hrow = hs + rg * RPG * KHH;

    // init h = 0 (pair shares 8 rows: gsel0 zeroes rows 0-3, gsel1 rows 4-7)
    for (int u = c; u < 4 * KHH; u += 32) hrow[gsel * 4 * KHH + u] = 0.f;
#pragma unroll
    for (int j = 0; j < 20; j++) cstS[j * NT + tid] = 0.f;

    ull acc[RPG][5];
    const ull* P8 = (const ull*)g_P;

    for (int t = 0; t < DEG; t++) {
        if (tid < TM) {
            int node = nodeBase + tid; if (node >= NN) node = NN - 1;
            srcS[tid] = esrc[node * DEG + t];
        }
        __syncthreads();

        // acc init = gather P plane [src] (coalesced 8B, lane-stride 8B)
#pragma unroll
        for (int i = 0; i < RPG; i++) {
            int s = srcS[rg * RPG + i];
            const ull* pb = P8 + s * 320 + gsel * 160;
#pragma unroll
            for (int n = 0; n < 5; n++) acc[i][n] = pb[n * 32 + c];
        }

        gemm160(g_WhhP, wsbase, hrow, tid, c, gsel, acc);

        // ---- exchange: send the 4 rows the partner updates
#pragma unroll
        for (int i = 0; i < 4; i++)
#pragma unroll
            for (int n = 0; n < 5; n++)
                exch[(i * 5 + n) * NT + tid] = acc[((1 - gsel) << 2) + i][n];
        __syncthreads();
        const int pt = tid ^ 32;

        // ---- update my 4 rows (rows gsel*4 .. gsel*4+3 of the group)
#pragma unroll
        for (int i = 0; i < 4; i++) {
#pragma unroll
            for (int n = 0; n < 5; n++) {
                ull own = acc[(gsel << 2) + i][n];
                ull oth = exch[(i * 5 + n) * NT + pt];
                float gi, gf, gg, go;
                if (gsel == 0) { unpack2(own, gi, gf); unpack2(oth, gg, go); }
                else           { unpack2(oth, gi, gf); unpack2(own, gg, go); }
                float iv = sigm(gi), fv = sigm(gf), ov = sigm(go);
                float gv = tanhfast(gg);
                int j = i * 5 + n;
                float cv = fv * cstS[j * NT + tid] + iv * gv;
                cstS[j * NT + tid] = cv;
                hrow[((gsel << 2) + i) * KHH + n * 32 + c] = ov * tanhfast(cv);
            }
        }
        // top-of-loop __syncthreads orders h writes / exch reuse
    }

    // ---- final layer: out = relu(Q[node] + h @ Wl^T), 4 rows per warp
    __syncthreads();
    float* Wfs = hs + TM * KHH;
    for (int u = tid; u < KHH * OC / 4; u += NT)
        ((float4*)Wfs)[u] = ((const float4*)g_WlP)[u];
    __syncthreads();

    float4 q[4];
#pragma unroll
    for (int i = 0; i < 4; i++) {
        int nc = nodeBase + rg * RPG + gsel * 4 + i; if (nc >= NN) nc = NN - 1;
        q[i] = ((const float4*)g_Q)[nc * 32 + c];
    }
    for (int k = 0; k < KHH; k++) {
        float4 w = ((const float4*)Wfs)[k * 32 + c];
#pragma unroll
        for (int i = 0; i < 4; i++) {
            float a = hrow[(gsel * 4 + i) * KHH + k];
            q[i].x = fmaf(a, w.x, q[i].x);
            q[i].y = fmaf(a, w.y, q[i].y);
            q[i].z = fmaf(a, w.z, q[i].z);
            q[i].w = fmaf(a, w.w, q[i].w);
        }
    }
#pragma unroll
    for (int i = 0; i < 4; i++) {
        int node = nodeBase + rg * RPG + gsel * 4 + i;
        if (node < NN) {
            float4 o;
            o.x = fmaxf(q[i].x, 0.f); o.y = fmaxf(q[i].y, 0.f);
            o.z = fmaxf(q[i].z, 0.f); o.w = fmaxf(q[i].w, 0.f);
            ((float4*)out)[node * 32 + c] = o;
        }
    }
}

// ---------------- launch ----------------
extern "C" void kernel_launch(void* const* d_in, const int* in_sizes, int n_in,
                              void* d_out, int out_size) {
    const float* x    = (const float*)d_in[0];
    const int*   tids = (const int*)  d_in[1];
    const int*   eidx = (const int*)  d_in[2];   // [2][E]; row 0 = src
    const float* emb  = (const float*)d_in[3];
    const float* Wih  = (const float*)d_in[4];
    const float* Whh  = (const float*)d_in[5];
    const float* bih  = (const float*)d_in[6];
    const float* bhh  = (const float*)d_in[7];
    const float* Wl   = (const float*)d_in[8];
    const float* bl   = (const float*)d_in[9];
    const float* Wr   = (const float*)d_in[10];
    float* out = (float*)d_out;

    static bool attr_done = false;
    if (!attr_done) {
        cudaFuncSetAttribute(prep_PQ, cudaFuncAttributeMaxDynamicSharedMemorySize,
                             TM * KHH * 4 + 2 * CHB);
        cudaFuncSetAttribute(lstm_main, cudaFuncAttributeMaxDynamicSharedMemorySize,
                             SM_MAIN);
        attr_done = true;
    }

    prep_hin<<<(NN * FD + 255) / 256, 256>>>(x, tids, emb);
    prep_w<<<(KHH * GD + 255) / 256, 256>>>(Wih, Whh, bih, bhh, Wl, Wr);
    prep_PQ<<<(NN + TM - 1) / TM, NT, TM * KHH * 4 + 2 * CHB>>>(bl);
    lstm_main<<<(NN + TM - 1) / TM, NT, SM_MAIN>>>(eidx, out);
}

// round 8
// speedup vs baseline: 1.0002x; 1.0002x over previous
#include <cuda_runtime.h>
#include <cstdint>

#define NN   50000
#define DEG  16
#define FD   160
#define HD   160
#define GD   640          // 4*H
#define OC   128
#define KHH  160          // K of recurrence GEMM

#define TM   64           // nodes per CTA
#define NT   512          // threads
#define NW   16           // warps: 8 row-groups x 2 gate-halves
#define RPG  8            // rows per group (warp pair)
#define KC   16
#define NCH  (KHH/KC)     // 10
#define CHF  (KC*GD)      // floats per chunk = 10240
#define CHB  (CHF*4)      // bytes per chunk  = 40960

// ---------------- device scratch ----------------
__device__ float g_hin[NN * FD];
// weight layout: [k][gsel][m][pair]  gsel0 pair=(i,f), gsel1 pair=(g,o)
__device__ float g_WihP[KHH * GD];
__device__ float g_WhhP[KHH * GD];
__device__ float g_bias[GD];             // [gsel][m][pair]
__device__ float g_WlP[KHH * OC];        // [k][j]
__device__ float g_WrP[KHH * OC];        // [k][j]
__device__ float g_P[NN * GD];           // [node][gsel][m][pair]
__device__ float g_Q[NN * OC];           // hin@Wr + b_l

// ---------------- helpers ----------------
typedef unsigned long long ull;

__device__ __forceinline__ ull pack2(float lo, float hi) {
    ull v; asm("mov.b64 %0, {%1, %2};" : "=l"(v) : "f"(lo), "f"(hi)); return v;
}
__device__ __forceinline__ void unpack2(ull v, float& lo, float& hi) {
    asm("mov.b64 {%0, %1}, %2;" : "=f"(lo), "=f"(hi) : "l"(v));
}
__device__ __forceinline__ void fma2(ull& d, ull a, ull b) {
    asm("fma.rn.f32x2 %0, %1, %2, %0;" : "+l"(d) : "l"(a), "l"(b));
}
__device__ __forceinline__ ull lds64(uint32_t a) {
    ull v; asm("ld.shared.b64 %0, [%1];" : "=l"(v) : "r"(a)); return v;
}
__device__ __forceinline__ void cp16(uint32_t s, const void* g) {
    asm volatile("cp.async.ca.shared.global [%0], [%1], 16;" :: "r"(s), "l"(g));
}
__device__ __forceinline__ void cpcommit() { asm volatile("cp.async.commit_group;"); }
template<int N> __device__ __forceinline__ void cpwait() {
    asm volatile("cp.async.wait_group %0;" :: "n"(N));
}
__device__ __forceinline__ float sigm(float x) {
    return __fdividef(1.f, 1.f + __expf(-x));
}
__device__ __forceinline__ float tanhfast(float x) {
    return __fdividef(2.f, 1.f + __expf(-2.f * x)) - 1.f;
}

// NT=512: each thread copies 20 floats (5 x 16B) of a 40960B chunk
__device__ __forceinline__ void stage_chunk(const float* gsrc, uint32_t sdst, int tid) {
#pragma unroll
    for (int u = 0; u < 5; u++)
        cp16(sdst + (uint32_t)(tid * 16 + u * 8192), gsrc + tid * 4 + u * 2048);
    cpcommit();
}

// K=160 GEMM, gate-split: warp computes ONE gate pair (gsel) for 8 rows.
// acc[i][n] : row i, m = n*32+c, pair (lo,hi) = gates (2*gsel, 2*gsel+1)
__device__ __forceinline__ void gemm160(const float* __restrict__ gW, uint32_t wsbase,
                                        const float* __restrict__ hrow, int tid, int c,
                                        int gsel, ull acc[RPG][5]) {
    stage_chunk(gW, wsbase, tid);
    stage_chunk(gW + CHF, wsbase + CHB, tid);
    const uint32_t lbase = (uint32_t)(gsel * 1280 + c * 8);
    for (int ch = 0; ch < NCH; ch++) {
        if (ch == NCH - 1) cpwait<0>(); else cpwait<1>();
        __syncthreads();
        const uint32_t wb0 = wsbase + (uint32_t)(ch & 1) * CHB + lbase;
#pragma unroll
        for (int kh = 0; kh < KC / 2; kh++) {
            float2 af[RPG];
#pragma unroll
            for (int i = 0; i < RPG; i++)
                af[i] = *(const float2*)&hrow[i * KHH + ch * KC + kh * 2];
#pragma unroll
            for (int k2 = 0; k2 < 2; k2++) {
                ull a2[RPG];
#pragma unroll
                for (int i = 0; i < RPG; i++) {
                    float a = k2 ? af[i].y : af[i].x;
                    a2[i] = pack2(a, a);
                }
                const uint32_t wb = wb0 + (uint32_t)((kh * 2 + k2) * 2560);
#pragma unroll
                for (int n = 0; n < 5; n++) {
                    ull w = lds64(wb + (uint32_t)(n * 256));
#pragma unroll
                    for (int i = 0; i < RPG; i++) fma2(acc[i][n], a2[i], w);
                }
            }
        }
        __syncthreads();
        if (ch < NCH - 2) stage_chunk(gW + (ch + 2) * CHF, wsbase + (uint32_t)(ch & 1) * CHB, tid);
    }
}

// ---------------- prep kernels ----------------
__global__ void prep_hin(const float* __restrict__ x, const int* __restrict__ tids,
                         const float* __restrict__ emb) {
    int i = blockIdx.x * blockDim.x + threadIdx.x;
    if (i >= NN * FD) return;
    int n = i / FD, c = i % FD;
    g_hin[i] = (c < 128) ? x[n * 128 + c] : emb[tids[n] * 32 + (c - 128)];
}

__global__ void prep_w(const float* __restrict__ Wih, const float* __restrict__ Whh,
                       const float* __restrict__ bih, const float* __restrict__ bhh,
                       const float* __restrict__ Wl,  const float* __restrict__ Wr) {
    int i = blockIdx.x * blockDim.x + threadIdx.x;
    if (i < KHH * GD) {
        int k = i / GD, r = i % GD;
        int gs = r / 320, q = r % 320, m = q >> 1, p = q & 1;
        int gate = gs * 2 + p;
        int j = gate * HD + m;
        g_WihP[i] = Wih[j * FD + k];
        g_WhhP[i] = Whh[j * HD + k];
    }
    if (i < GD) {
        int gs = i / 320, q = i % 320, m = q >> 1, p = q & 1;
        int gate = gs * 2 + p;
        g_bias[i] = bih[gate * HD + m] + bhh[gate * HD + m];
    }
    if (i < KHH * OC) {
        int k = i / OC, j = i % OC;
        g_WlP[i] = Wl[j * FD + k];
        g_WrP[i] = Wr[j * FD + k];
    }
}

// P = hin@Wih^T + b (plane-split layout) ; Q = hin@Wr^T + b_l
__global__ void __launch_bounds__(NT, 1)
prep_PQ(const float* __restrict__ bl) {
    extern __shared__ float sm[];
    float* hs = sm;                       // [64][160]
    const uint32_t sbase = (uint32_t)__cvta_generic_to_shared(sm);
    const uint32_t wsbase = sbase + TM * KHH * 4;

    const int tid = threadIdx.x, c = tid & 31, warp = tid >> 5;
    const int rg = warp >> 1, gsel = warp & 1;
    const int nodeBase = blockIdx.x * TM;
    float* hrow = hs + rg * RPG * KHH;

    // load hin rows (clamped): 2560 float4 total
#pragma unroll
    for (int u = 0; u < 5; u++) {
        int idx4 = tid + u * NT;
        int r = idx4 / 40, col4 = idx4 % 40;
        int node = nodeBase + r; if (node >= NN) node = NN - 1;
        ((float4*)hs)[idx4] = ((const float4*)g_hin)[node * 40 + col4];
    }
    __syncthreads();

    ull acc[RPG][5];
    const ull* b8 = (const ull*)g_bias;
#pragma unroll
    for (int n = 0; n < 5; n++) {
        ull b = b8[gsel * 160 + n * 32 + c];
#pragma unroll
        for (int i = 0; i < RPG; i++) acc[i][n] = b;
    }
    gemm160(g_WihP, wsbase, hrow, tid, c, gsel, acc);

    ull* P8 = (ull*)g_P;
#pragma unroll
    for (int i = 0; i < RPG; i++) {
        int node = nodeBase + rg * RPG + i;
        if (node < NN) {
#pragma unroll
            for (int n = 0; n < 5; n++)
                P8[node * 320 + gsel * 160 + n * 32 + c] = acc[i][n];
        }
    }

    // ---- Q phase: stage full Wr into Ws region; each warp does 4 rows
    __syncthreads();
    float* Wfs = hs + TM * KHH;
    for (int u = tid; u < KHH * OC / 4; u += NT)
        ((float4*)Wfs)[u] = ((const float4*)g_WrP)[u];
    __syncthreads();

    float4 q[4];
    float4 blv = ((const float4*)bl)[c];
#pragma unroll
    for (int i = 0; i < 4; i++) q[i] = blv;
    for (int k = 0; k < KHH; k++) {
        float4 w = ((const float4*)Wfs)[k * 32 + c];
#pragma unroll
        for (int i = 0; i < 4; i++) {
            float a = hrow[(gsel * 4 + i) * KHH + k];
            q[i].x = fmaf(a, w.x, q[i].x);
            q[i].y = fmaf(a, w.y, q[i].y);
            q[i].z = fmaf(a, w.z, q[i].z);
            q[i].w = fmaf(a, w.w, q[i].w);
        }
    }
#pragma unroll
    for (int i = 0; i < 4; i++) {
        int node = nodeBase + rg * RPG + gsel * 4 + i;
        if (node < NN) ((float4*)g_Q)[node * 32 + c] = q[i];
    }
}

// ---------------- main recurrence kernel ----------------
// smem: hs[64*160] | Ws[2][10240] (doubles as exchange buffer) | cst[20*512] | src[64]
#define SM_MAIN (TM*KHH*4 + 2*CHB + 20*NT*4 + TM*4)

__global__ void __launch_bounds__(NT, 1)
lstm_main(const int* __restrict__ esrc, float* __restrict__ out) {
    extern __shared__ float sm[];
    float* hs   = sm;
    ull*   exch = (ull*)(sm + TM * KHH);        // aliases Ws region (dead between GEMMs)
    float* cstS = sm + TM * KHH + 2 * CHF;
    int*   srcS = (int*)(cstS + 20 * NT);
    const uint32_t sbase  = (uint32_t)__cvta_generic_to_shared(sm);
    const uint32_t wsbase = sbase + TM * KHH * 4;

    const int tid = threadIdx.x, c = tid & 31, warp = tid >> 5;
    const int rg = warp >> 1, gsel = warp & 1;
    const int nodeBase = blockIdx.x * TM;
    float* hrow = hs + rg * RPG * KHH;

    // init h = 0 (pair shares 8 rows: gsel0 zeroes rows 0-3, gsel1 rows 4-7)
    for (int u = c; u < 4 * KHH; u += 32) hrow[gsel * 4 * KHH + u] = 0.f;
#pragma unroll
    for (int j = 0; j < 20; j++) cstS[j * NT + tid] = 0.f;

    ull acc[RPG][5];
    const ull* P8 = (const ull*)g_P;

    for (int t = 0; t < DEG; t++) {
        if (tid < TM) {
            int node = nodeBase + tid; if (node >= NN) node = NN - 1;
            srcS[tid] = esrc[node * DEG + t];
        }
        __syncthreads();

        // acc init = gather P plane [src] (coalesced 8B, lane-stride 8B)
#pragma unroll
        for (int i = 0; i < RPG; i++) {
            int s = srcS[rg * RPG + i];
            const ull* pb = P8 + s * 320 + gsel * 160;
#pragma unroll
            for (int n = 0; n < 5; n++) acc[i][n] = pb[n * 32 + c];
        }

        gemm160(g_WhhP, wsbase, hrow, tid, c, gsel, acc);

        // ---- exchange: send the 4 rows the partner updates
#pragma unroll
        for (int i = 0; i < 4; i++)
#pragma unroll
            for (int n = 0; n < 5; n++)
                exch[(i * 5 + n) * NT + tid] = acc[((1 - gsel) << 2) + i][n];
        __syncthreads();
        const int pt = tid ^ 32;

        // ---- update my 4 rows (rows gsel*4 .. gsel*4+3 of the group)
#pragma unroll
        for (int i = 0; i < 4; i++) {
#pragma unroll
            for (int n = 0; n < 5; n++) {
                ull own = acc[(gsel << 2) + i][n];
                ull oth = exch[(i * 5 + n) * NT + pt];
                float gi, gf, gg, go;
                if (gsel == 0) { unpack2(own, gi, gf); unpack2(oth, gg, go); }
                else           { unpack2(oth, gi, gf); unpack2(own, gg, go); }
                float iv = sigm(gi), fv = sigm(gf), ov = sigm(go);
                float gv = tanhfast(gg);
                int j = i * 5 + n;
                float cv = fv * cstS[j * NT + tid] + iv * gv;
                cstS[j * NT + tid] = cv;
                hrow[((gsel << 2) + i) * KHH + n * 32 + c] = ov * tanhfast(cv);
            }
        }
        // top-of-loop __syncthreads orders h writes / exch reuse
    }

    // ---- final layer: out = relu(Q[node] + h @ Wl^T), 4 rows per warp
    __syncthreads();
    float* Wfs = hs + TM * KHH;
    for (int u = tid; u < KHH * OC / 4; u += NT)
        ((float4*)Wfs)[u] = ((const float4*)g_WlP)[u];
    __syncthreads();

    float4 q[4];
#pragma unroll
    for (int i = 0; i < 4; i++) {
        int nc = nodeBase + rg * RPG + gsel * 4 + i; if (nc >= NN) nc = NN - 1;
        q[i] = ((const float4*)g_Q)[nc * 32 + c];
    }
    for (int k = 0; k < KHH; k++) {
        float4 w = ((const float4*)Wfs)[k * 32 + c];
#pragma unroll
        for (int i = 0; i < 4; i++) {
            float a = hrow[(gsel * 4 + i) * KHH + k];
            q[i].x = fmaf(a, w.x, q[i].x);
            q[i].y = fmaf(a, w.y, q[i].y);
            q[i].z = fmaf(a, w.z, q[i].z);
            q[i].w = fmaf(a, w.w, q[i].w);
        }
    }
#pragma unroll
    for (int i = 0; i < 4; i++) {
        int node = nodeBase + rg * RPG + gsel * 4 + i;
        if (node < NN) {
            float4 o;
            o.x = fmaxf(q[i].x, 0.f); o.y = fmaxf(q[i].y, 0.f);
            o.z = fmaxf(q[i].z, 0.f); o.w = fmaxf(q[i].w, 0.f);
            ((float4*)out)[node * 32 + c] = o;
        }
    }
}

// ---------------- launch ----------------
extern "C" void kernel_launch(void* const* d_in, const int* in_sizes, int n_in,
                              void* d_out, int out_size) {
    const float* x    = (const float*)d_in[0];
    const int*   tids = (const int*)  d_in[1];
    const int*   eidx = (const int*)  d_in[2];   // [2][E]; row 0 = src
    const float* emb  = (const float*)d_in[3];
    const float* Wih  = (const float*)d_in[4];
    const float* Whh  = (const float*)d_in[5];
    const float* bih  = (const float*)d_in[6];
    const float* bhh  = (const float*)d_in[7];
    const float* Wl   = (const float*)d_in[8];
    const float* bl   = (const float*)d_in[9];
    const float* Wr   = (const float*)d_in[10];
    float* out = (float*)d_out;

    static bool attr_done = false;
    if (!attr_done) {
        cudaFuncSetAttribute(prep_PQ, cudaFuncAttributeMaxDynamicSharedMemorySize,
                             TM * KHH * 4 + 2 * CHB);
        cudaFuncSetAttribute(lstm_main, cudaFuncAttributeMaxDynamicSharedMemorySize,
                             SM_MAIN);
        attr_done = true;
    }

    prep_hin<<<(NN * FD + 255) / 256, 256>>>(x, tids, emb);
    prep_w<<<(KHH * GD + 255) / 256, 256>>>(Wih, Whh, bih, bhh, Wl, Wr);
    prep_PQ<<<(NN + TM - 1) / TM, NT, TM * KHH * 4 + 2 * CHB>>>(bl);
    lstm_main<<<(NN + TM - 1) / TM, NT, SM_MAIN>>>(eidx, out);
}

// round 9
// speedup vs baseline: 1.6488x; 1.6484x over previous
#include <cuda_runtime.h>
#include <cuda_bf16.h>
#include <cstdint>

#define NN   50000
#define DEG  16
#define FD   160
#define HD   160
#define GD   640
#define OC   128
#define KHH  160

// prep (fp32) config — proven round-6 machinery
#define PTM  64
#define PNT  512
#define PKC  16
#define PNCH (KHH/PKC)
#define PCHF (PKC*GD)
#define PCHB (PCHF*4)

// main MMA kernel config
#define TM   64
#define NT   256
// smem byte offsets
#define HPLANE 21504               // 64*168*2B per plane
#define HBUF   43008               // 2 planes
#define SM_B   86016               // B double buffer: 2 x 12800
#define SM_CST 111616              // 40*256*4 = 40960
#define SM_SRC 152576              // 64*4
#define SM_MAIN 152832

typedef unsigned long long ull;

// ---------------- device scratch ----------------
__device__ float g_hin[NN * FD];
__device__ float g_WihP[KHH * HD * 4];   // [k][m][4]
__device__ float g_bias[GD];             // [m][4]
__device__ float g_WlP[KHH * OC];
__device__ float g_WrP[KHH * OC];
__device__ float g_P[NN * GD];           // [node][4m+g]
__device__ float g_Q[NN * OC];
// Whh bf16 split: [pl 2][q 4][kc 10][n 160][20 (16k+4pad)]
__device__ __align__(16) __nv_bfloat16 g_Wb[2 * 4 * 10 * 160 * 20];

// ---------------- helpers ----------------
__device__ __forceinline__ ull pack2(float lo, float hi) {
    ull v; asm("mov.b64 %0, {%1, %2};" : "=l"(v) : "f"(lo), "f"(hi)); return v;
}
__device__ __forceinline__ void unpack2(ull v, float& lo, float& hi) {
    asm("mov.b64 {%0, %1}, %2;" : "=f"(lo), "=f"(hi) : "l"(v));
}
__device__ __forceinline__ void fma2(ull& d, ull a, ull b) {
    asm("fma.rn.f32x2 %0, %1, %2, %0;" : "+l"(d) : "l"(a), "l"(b));
}
__device__ __forceinline__ void ldsv2(uint32_t a, ull& x, ull& y) {
    asm("ld.shared.v2.u64 {%0,%1}, [%2];" : "=l"(x), "=l"(y) : "r"(a));
}
__device__ __forceinline__ uint32_t lds32(uint32_t a) {
    uint32_t v; asm("ld.shared.b32 %0, [%1];" : "=r"(v) : "r"(a)); return v;
}
__device__ __forceinline__ void cp16(uint32_t s, const void* g) {
    asm volatile("cp.async.ca.shared.global [%0], [%1], 16;" :: "r"(s), "l"(g));
}
__device__ __forceinline__ void cpcommit() { asm volatile("cp.async.commit_group;"); }
template<int N> __device__ __forceinline__ void cpwait() {
    asm volatile("cp.async.wait_group %0;" :: "n"(N));
}
__device__ __forceinline__ float sigm(float x) { return __fdividef(1.f, 1.f + __expf(-x)); }
__device__ __forceinline__ float tanhfast(float x) {
    return __fdividef(2.f, 1.f + __expf(-2.f * x)) - 1.f;
}
__device__ __forceinline__ void mma_bf16(float* d, const uint32_t* a, uint32_t b0, uint32_t b1) {
    asm volatile("mma.sync.aligned.m16n8k16.row.col.f32.bf16.bf16.f32 "
                 "{%0,%1,%2,%3}, {%4,%5,%6,%7}, {%8,%9}, {%0,%1,%2,%3};"
                 : "+f"(d[0]), "+f"(d[1]), "+f"(d[2]), "+f"(d[3])
                 : "r"(a[0]), "r"(a[1]), "r"(a[2]), "r"(a[3]), "r"(b0), "r"(b1));
}

// ---------------- prep kernels ----------------
__global__ void prep_hin(const float* __restrict__ x, const int* __restrict__ tids,
                         const float* __restrict__ emb) {
    int i = blockIdx.x * blockDim.x + threadIdx.x;
    if (i >= NN * FD) return;
    int n = i / FD, c = i % FD;
    g_hin[i] = (c < 128) ? x[n * 128 + c] : emb[tids[n] * 32 + (c - 128)];
}

__global__ void prep_w(const float* __restrict__ Wih,
                       const float* __restrict__ bih, const float* __restrict__ bhh,
                       const float* __restrict__ Wl,  const float* __restrict__ Wr) {
    int i = blockIdx.x * blockDim.x + threadIdx.x;
    if (i < KHH * HD * 4) {
        int g = i & 3, m = (i >> 2) % HD, k = (i >> 2) / HD;
        g_WihP[i] = Wih[(g * HD + m) * FD + k];
    }
    if (i < GD) {
        int m = i >> 2, g = i & 3;
        g_bias[i] = bih[g * HD + m] + bhh[g * HD + m];
    }
    if (i < KHH * OC) {
        int k = i / OC, j = i % OC;
        g_WlP[i] = Wl[j * FD + k];
        g_WrP[i] = Wr[j * FD + k];
    }
}

// bf16 hi/lo split + transpose of Whh into [pl][q][kc][n][20]
__global__ void prep_wb(const float* __restrict__ Whh) {
    int i = blockIdx.x * blockDim.x + threadIdx.x;
    if (i >= 2 * 4 * 10 * 160 * 20) return;
    int kk = i % 20;
    int n  = (i / 20) % 160;
    int kc = (i / 3200) % 10;
    int q  = (i / 32000) % 4;
    int pl = i / 128000;
    if (kk >= 16) { g_Wb[i] = __float2bfloat16(0.f); return; }
    int k = kc * 16 + kk;
    int gcl = q * 160 + n;
    int m = gcl >> 2, g = gcl & 3;
    float w = Whh[(g * HD + m) * HD + k];
    __nv_bfloat16 hb = __float2bfloat16(w);
    g_Wb[i] = pl ? __float2bfloat16(w - __bfloat162float(hb)) : hb;
}

// ---- prep_PQ: fp32 K=160 GEMM (proven) ----
__device__ __forceinline__ void pstage(const float* gsrc, uint32_t sdst, int tid) {
#pragma unroll
    for (int u = 0; u < 5; u++)
        cp16(sdst + (uint32_t)(tid * 16 + u * 8192), gsrc + tid * 4 + u * 2048);
    cpcommit();
}
__device__ __forceinline__ void pgemm(const float* __restrict__ gW, uint32_t wsbase,
                                      const float* __restrict__ hrow, int tid, int c,
                                      ull accIF[4][5], ull accGO[4][5]) {
    pstage(gW, wsbase, tid);
    pstage(gW + PCHF, wsbase + PCHB, tid);
    for (int ch = 0; ch < PNCH; ch++) {
        if (ch == PNCH - 1) cpwait<0>(); else cpwait<1>();
        __syncthreads();
        const uint32_t wb0 = wsbase + (uint32_t)(ch & 1) * PCHB;
#pragma unroll
        for (int kq = 0; kq < 4; kq++) {
            float4 a4[4];
#pragma unroll
            for (int i = 0; i < 4; i++)
                a4[i] = *(const float4*)&hrow[i * KHH + ch * PKC + kq * 4];
#pragma unroll
            for (int k2 = 0; k2 < 4; k2++) {
                ull a2[4];
#pragma unroll
                for (int i = 0; i < 4; i++) {
                    float a = (k2 == 0) ? a4[i].x : (k2 == 1) ? a4[i].y
                             : (k2 == 2) ? a4[i].z : a4[i].w;
                    a2[i] = pack2(a, a);
                }
                const uint32_t wb = wb0 + (uint32_t)((kq * 4 + k2) * 2560 + c * 16);
#pragma unroll
                for (int n = 0; n < 5; n++) {
                    ull wif, wgo;
                    ldsv2(wb + (uint32_t)(n * 512), wif, wgo);
#pragma unroll
                    for (int i = 0; i < 4; i++) {
                        fma2(accIF[i][n], a2[i], wif);
                        fma2(accGO[i][n], a2[i], wgo);
                    }
                }
            }
        }
        __syncthreads();
        if (ch < PNCH - 2) pstage(gW + (ch + 2) * PCHF, wsbase + (uint32_t)(ch & 1) * PCHB, tid);
    }
}

__global__ void __launch_bounds__(PNT, 1)
prep_PQ(const float* __restrict__ bl) {
    extern __shared__ float sm[];
    float* hs = sm;
    const uint32_t sbase = (uint32_t)__cvta_generic_to_shared(sm);
    const uint32_t wsbase = sbase + PTM * KHH * 4;
    const int tid = threadIdx.x, c = tid & 31, warp = tid >> 5;
    const int nodeBase = blockIdx.x * PTM;
    float* hrow = hs + warp * 4 * KHH;

#pragma unroll
    for (int u = 0; u < 5; u++) {
        int idx4 = tid + u * PNT;
        int r = idx4 / 40, col4 = idx4 % 40;
        int node = nodeBase + r; if (node >= NN) node = NN - 1;
        ((float4*)hs)[idx4] = ((const float4*)g_hin)[node * 40 + col4];
    }
    __syncthreads();

    ull accIF[4][5], accGO[4][5];
#pragma unroll
    for (int n = 0; n < 5; n++) {
        float4 b = ((const float4*)g_bias)[n * 32 + c];
#pragma unroll
        for (int i = 0; i < 4; i++) {
            accIF[i][n] = pack2(b.x, b.y);
            accGO[i][n] = pack2(b.z, b.w);
        }
    }
    pgemm(g_WihP, wsbase, hrow, tid, c, accIF, accGO);

#pragma unroll
    for (int i = 0; i < 4; i++) {
        int node = nodeBase + warp * 4 + i;
        if (node < NN) {
#pragma unroll
            for (int n = 0; n < 5; n++) {
                float4 o;
                unpack2(accIF[i][n], o.x, o.y);
                unpack2(accGO[i][n], o.z, o.w);
                ((float4*)g_P)[node * 160 + n * 32 + c] = o;
            }
        }
    }

    __syncthreads();
    float* Wfs = hs + PTM * KHH;
    for (int u = tid; u < KHH * OC / 4; u += PNT)
        ((float4*)Wfs)[u] = ((const float4*)g_WrP)[u];
    __syncthreads();

    float4 q[4];
    float4 blv = ((const float4*)bl)[c];
#pragma unroll
    for (int i = 0; i < 4; i++) q[i] = blv;
    for (int k = 0; k < KHH; k++) {
        float4 w = ((const float4*)Wfs)[k * 32 + c];
#pragma unroll
        for (int i = 0; i < 4; i++) {
            float a = hrow[i * KHH + k];
            q[i].x = fmaf(a, w.x, q[i].x);
            q[i].y = fmaf(a, w.y, q[i].y);
            q[i].z = fmaf(a, w.z, q[i].z);
            q[i].w = fmaf(a, w.w, q[i].w);
        }
    }
#pragma unroll
    for (int i = 0; i < 4; i++) {
        int node = nodeBase + warp * 4 + i;
        if (node < NN) ((float4*)g_Q)[node * 32 + c] = q[i];
    }
}

// ---------------- main MMA recurrence kernel ----------------
__device__ __forceinline__ void stageB(uint32_t sdst, const __nv_bfloat16* gsrc, int tid) {
#pragma unroll
    for (int u = 0; u < 3; u++)
        cp16(sdst + (uint32_t)((tid + u * 256) * 16), gsrc + (tid + u * 256) * 8);
    if (tid < 32) cp16(sdst + (uint32_t)((768 + tid) * 16), gsrc + (768 + tid) * 8);
    cpcommit();
}

__global__ void __launch_bounds__(NT, 1)
lstm_main(const int* __restrict__ esrc, float* __restrict__ out) {
    extern __shared__ char smraw[];
    __nv_bfloat16* hB = (__nv_bfloat16*)smraw;                 // [2buf][2pl][64][168]
    float* cst = (float*)(smraw + SM_CST);
    int*   srcS = (int*)(smraw + SM_SRC);
    const uint32_t sbase = (uint32_t)__cvta_generic_to_shared(smraw);

    const int tid = threadIdx.x, lane = tid & 31, warp = tid >> 5;
    const int q2 = lane & 3, r8 = lane >> 2;
    const int mg = warp & 1, ng = warp >> 1;
    const int nodeBase = blockIdx.x * TM;

    for (int i = tid; i < 2 * 10752; i += NT) hB[i] = __float2bfloat16(0.f);
#pragma unroll
    for (int j = 0; j < 40; j++) cst[j * NT + tid] = 0.f;

    for (int t = 0; t < DEG; t++) {
        if (tid < TM) {
            int node = nodeBase + tid; if (node >= NN) node = NN - 1;
            srcS[tid] = esrc[node * DEG + t];
        }
        __syncthreads();

        const uint32_t hRd = sbase + (uint32_t)(t & 1) * HBUF;
        __nv_bfloat16* hWr = hB + ((t + 1) & 1) * (HBUF / 2);

        for (int q = 0; q < 4; q++) {
            // acc init from P (bias folded in)
            float acc[2][5][4];
            const int gb = q * 160 + ng * 40 + q2 * 2;
#pragma unroll
            for (int mt = 0; mt < 2; mt++) {
                int rr = mg * 32 + mt * 16 + r8;
                const float* p0 = g_P + (size_t)srcS[rr] * 640 + gb;
                const float* p8 = g_P + (size_t)srcS[rr + 8] * 640 + gb;
#pragma unroll
                for (int nt = 0; nt < 5; nt++) {
                    float2 v0 = *(const float2*)(p0 + nt * 8);
                    float2 v8 = *(const float2*)(p8 + nt * 8);
                    acc[mt][nt][0] = v0.x; acc[mt][nt][1] = v0.y;
                    acc[mt][nt][2] = v8.x; acc[mt][nt][3] = v8.y;
                }
            }

            // chunk source: stage st -> term = st/5 (0:hh 1:hl 2:lh), kc pair = (st%5)*2
            const __nv_bfloat16* Wq0 = g_Wb + (size_t)q * 32000;          // hi plane, this q
            const __nv_bfloat16* Wq1 = g_Wb + 128000 + (size_t)q * 32000; // lo plane
            stageB(sbase + SM_B, Wq0, tid);
            stageB(sbase + SM_B + 12800, Wq0 + 6400, tid);

            for (int st = 0; st < 15; st++) {
                if (st == 14) cpwait<0>(); else cpwait<1>();
                __syncthreads();
                const uint32_t aPl = hRd + ((st >= 10) ? HPLANE : 0);
                const uint32_t bB = sbase + SM_B + (uint32_t)(st & 1) * 12800;
                const int kb = (st % 5) * 32;
#pragma unroll
                for (int sub = 0; sub < 2; sub++) {
                    uint32_t af[2][4];
#pragma unroll
                    for (int mt = 0; mt < 2; mt++) {
                        uint32_t a0 = aPl + (uint32_t)(((mg * 32 + mt * 16 + r8) * 168
                                                        + kb + sub * 16 + q2 * 2) * 2);
                        af[mt][0] = lds32(a0);
                        af[mt][1] = lds32(a0 + 8 * 336);
                        af[mt][2] = lds32(a0 + 16);
                        af[mt][3] = lds32(a0 + 8 * 336 + 16);
                    }
#pragma unroll
                    for (int nt = 0; nt < 5; nt++) {
                        uint32_t ba = bB + (uint32_t)(sub * 6400
                                       + ((ng * 40 + nt * 8 + r8) * 20 + q2 * 2) * 2);
                        uint32_t b0 = lds32(ba), b1 = lds32(ba + 16);
                        mma_bf16(acc[0][nt], af[0], b0, b1);
                        mma_bf16(acc[1][nt], af[1], b0, b1);
                    }
                }
                __syncthreads();
                if (st < 13) {
                    int s2 = st + 2;
                    const __nv_bfloat16* src = ((s2 >= 5 && s2 < 10) ? Wq1 : Wq0)
                                               + (s2 % 5) * 6400;
                    stageB(sbase + SM_B + (uint32_t)(st & 1) * 12800, src, tid);
                }
            }

            // pointwise: lane pair (i,f)|(g,o) exchange via shfl_xor(1)
#pragma unroll
            for (int mt = 0; mt < 2; mt++) {
                int rw = mg * 32 + mt * 16 + r8 + ((q2 & 1) ? 8 : 0);
#pragma unroll
                for (int nt = 0; nt < 5; nt++) {
                    float ox = __shfl_xor_sync(0xffffffff, acc[mt][nt][0], 1);
                    float oy = __shfl_xor_sync(0xffffffff, acc[mt][nt][1], 1);
                    float oz = __shfl_xor_sync(0xffffffff, acc[mt][nt][2], 1);
                    float ow = __shfl_xor_sync(0xffffffff, acc[mt][nt][3], 1);
                    float gi, gf, gg, go;
                    if (!(q2 & 1)) { gi = acc[mt][nt][0]; gf = acc[mt][nt][1]; gg = ox; go = oy; }
                    else           { gi = oz; gf = ow; gg = acc[mt][nt][2]; go = acc[mt][nt][3]; }
                    int m = q * 40 + ng * 10 + nt * 2 + (q2 >> 1);
                    int slot = q * 10 + mt * 5 + nt;
                    float cv = sigm(gf) * cst[slot * NT + tid] + sigm(gi) * tanhfast(gg);
                    cst[slot * NT + tid] = cv;
                    float hv = sigm(go) * tanhfast(cv);
                    __nv_bfloat16 hh = __float2bfloat16(hv);
                    hWr[rw * 168 + m] = hh;
                    hWr[10752 + rw * 168 + m] =
                        __float2bfloat16(hv - __bfloat162float(hh));
                }
            }
        }
    }

    // ---- final layer: out = relu(Q[node] + h @ Wl^T), h in buf0 (t=15 wrote buf0)
    __syncthreads();
    const __nv_bfloat16* hf = hB;               // buf0 hi
    const __nv_bfloat16* hl = hB + 10752;       // buf0 lo
#pragma unroll
    for (int r = 0; r < 8; r++) {
        int row = warp * 8 + r;
        int node = nodeBase + row;
        int nc = node < NN ? node : NN - 1;
        float4 qv = ((const float4*)g_Q)[nc * 32 + lane];
        for (int k = 0; k < KHH; k++) {
            float a = __bfloat162float(hf[row * 168 + k]) +
                      __bfloat162float(hl[row * 168 + k]);
            float4 w = *(const float4*)&g_WlP[k * OC + lane * 4];
            qv.x = fmaf(a, w.x, qv.x);
            qv.y = fmaf(a, w.y, qv.y);
            qv.z = fmaf(a, w.z, qv.z);
            qv.w = fmaf(a, w.w, qv.w);
        }
        if (node < NN) {
            float4 o;
            o.x = fmaxf(qv.x, 0.f); o.y = fmaxf(qv.y, 0.f);
            o.z = fmaxf(qv.z, 0.f); o.w = fmaxf(qv.w, 0.f);
            ((float4*)out)[node * 32 + lane] = o;
        }
    }
}

// ---------------- launch ----------------
extern "C" void kernel_launch(void* const* d_in, const int* in_sizes, int n_in,
                              void* d_out, int out_size) {
    const float* x    = (const float*)d_in[0];
    const int*   tids = (const int*)  d_in[1];
    const int*   eidx = (const int*)  d_in[2];
    const float* emb  = (const float*)d_in[3];
    const float* Wih  = (const float*)d_in[4];
    const float* Whh  = (const float*)d_in[5];
    const float* bih  = (const float*)d_in[6];
    const float* bhh  = (const float*)d_in[7];
    const float* Wl   = (const float*)d_in[8];
    const float* bl   = (const float*)d_in[9];
    const float* Wr   = (const float*)d_in[10];
    float* out = (float*)d_out;

    static bool attr_done = false;
    if (!attr_done) {
        cudaFuncSetAttribute(prep_PQ, cudaFuncAttributeMaxDynamicSharedMemorySize,
                             PTM * KHH * 4 + 2 * PCHB);
        cudaFuncSetAttribute(lstm_main, cudaFuncAttributeMaxDynamicSharedMemorySize,
                             SM_MAIN);
        attr_done = true;
    }

    prep_hin<<<(NN * FD + 255) / 256, 256>>>(x, tids, emb);
    prep_w<<<(KHH * HD * 4 + 255) / 256, 256>>>(Wih, bih, bhh, Wl, Wr);
    prep_wb<<<(2 * 4 * 10 * 160 * 20 + 255) / 256, 256>>>(Whh);
    prep_PQ<<<(NN + PTM - 1) / PTM, PNT, PTM * KHH * 4 + 2 * PCHB>>>(bl);
    lstm_main<<<(NN + TM - 1) / TM, NT, SM_MAIN>>>(eidx, out);
}